// round 10
// baseline (speedup 1.0000x reference)
#include <cuda_runtime.h>
#include <math.h>
#include <stdint.h>

#define B_SZ   32
#define NTOK   3136
#define DMODEL 384
#define HEADS  8
#define CDIM   48
#define BKT    16
#define KITERS (DMODEL / BKT)   // 24

// Scratch (static device globals — allocation-free rule)
__device__ float g_qkv[(size_t)3 * B_SZ * DMODEL * NTOK];   // [3][B][384][N]
__device__ float g_rnorm[2 * B_SZ * DMODEL];                // [2][B][384]
__device__ float g_ctx[(size_t)B_SZ * NTOK * DMODEL];       // [B][N][D] bn-major
__device__ float g_attnp[7 * 256 * CDIM * CDIM];            // partial QK^T sums
__device__ float g_attn[256 * CDIM * CDIM];                 // softmaxed attn

__device__ __forceinline__ uint32_t f2tf32(float x) {
    uint32_t r; asm("cvt.rna.tf32.f32 %0, %1;" : "=r"(r) : "f"(x)); return r;
}
__device__ __forceinline__ uint4 cvt4(float4 t) {
    return make_uint4(f2tf32(t.x), f2tf32(t.y), f2tf32(t.z), f2tf32(t.w));
}
__device__ __forceinline__ void mma_tf32(float* d, const uint32_t* a, const uint32_t* b) {
    asm volatile(
        "mma.sync.aligned.m16n8k8.row.col.f32.tf32.tf32.f32 "
        "{%0,%1,%2,%3}, {%4,%5,%6,%7}, {%8,%9}, {%0,%1,%2,%3};\n"
        : "+f"(d[0]), "+f"(d[1]), "+f"(d[2]), "+f"(d[3])
        : "r"(a[0]), "r"(a[1]), "r"(a[2]), "r"(a[3]), "r"(b[0]), "r"(b[1]));
}

typedef uint32_t SmTile[128][20];

// ---------------------------------------------------------------------------
// Hybrid 128x128x384 mainloop.
// Warps 0-7 (tensor): cols 0..95 via mma.sync tf32, acc[(i*3+j)*4 + r].
// Warps 8-11 (FFMA): cols 96..127 in fp32 SIMT,     acc[s*4 + j].
// A rows from aB (row-major, ld=384), B rows from bB (row-major, ld=384).
// ---------------------------------------------------------------------------
__device__ __forceinline__ void hybrid_loop(
    const float* __restrict__ aB, const float* __restrict__ bB,
    SmTile* As, SmTile* Ws, float (&acc)[48], int tid)
{
    const int lane = tid & 31;
    const int warp = tid >> 5;
    const bool isT = warp < 8;

#pragma unroll
    for (int i = 0; i < 48; i++) acc[i] = 0.f;

    // tensor-warp load slots (A tile): rows tid>>2 and +64, quad tid&3
    const int rowA = tid >> 2;
    const int qd   = tid & 3;
    // ffma-warp load slots (B tile): rows (ftid>>2)+32r, quad ftid&3
    const int ftid = tid - 256;
    const int rowB = (ftid >> 2);
    const int qdB  = ftid & 3;

    const float* ap0 = aB + (size_t)rowA * DMODEL + qd * 4;
    const float* ap1 = aB + (size_t)(rowA + 64) * DMODEL + qd * 4;
    const float* bp0 = bB + (size_t)rowB * DMODEL + qdB * 4;

    float4 ra0, ra1, rb[4];
    if (isT) {
        ra0 = *(const float4*)ap0;
        ra1 = *(const float4*)ap1;
        *(uint4*)&As[0][rowA][qd * 4]      = cvt4(ra0);
        *(uint4*)&As[0][rowA + 64][qd * 4] = cvt4(ra1);
    } else {
#pragma unroll
        for (int r = 0; r < 4; r++) {
            rb[r] = *(const float4*)(bp0 + (size_t)(32 * r) * DMODEL);
            *(uint4*)&Ws[0][rowB + 32 * r][qdB * 4] = cvt4(rb[r]);
        }
    }
    __syncthreads();

    // tensor fragment indices
    const int gid = lane >> 2;
    const int tig = lane & 3;
    const int wm  = warp >> 2;   // 0..1 (tensor only)
    const int wn  = warp & 3;    // 0..3
    // ffma indices
    const int fw = warp - 8;            // 0..3
    const int rl = lane & 7;
    const int cg = lane >> 3;
    const int rowHalf = (fw >> 1) * 64;
    const int colB    = 96 + (fw & 1) * 16 + cg * 4;

    for (int kt = 0; kt < KITERS; kt++) {
        const int cur = kt & 1;
        if (kt + 1 < KITERS) {
            const int kb = (kt + 1) * BKT;
            if (isT) {
                ra0 = *(const float4*)(ap0 + kb);
                ra1 = *(const float4*)(ap1 + kb);
            } else {
#pragma unroll
                for (int r = 0; r < 4; r++)
                    rb[r] = *(const float4*)(bp0 + (size_t)(32 * r) * DMODEL + kb);
            }
        }
        if (isT) {
#pragma unroll
            for (int ks = 0; ks < 2; ks++) {
                const int k0 = ks * 8;
                uint32_t af[4][4], bf[3][2];
#pragma unroll
                for (int i = 0; i < 4; i++) {
                    int m = wm * 64 + i * 16;
                    af[i][0] = As[cur][m + gid][k0 + tig];
                    af[i][1] = As[cur][m + gid + 8][k0 + tig];
                    af[i][2] = As[cur][m + gid][k0 + tig + 4];
                    af[i][3] = As[cur][m + gid + 8][k0 + tig + 4];
                }
#pragma unroll
                for (int j = 0; j < 3; j++) {
                    int n = wn * 24 + j * 8;
                    bf[j][0] = Ws[cur][n + gid][k0 + tig];
                    bf[j][1] = Ws[cur][n + gid][k0 + tig + 4];
                }
#pragma unroll
                for (int i = 0; i < 4; i++)
#pragma unroll
                    for (int j = 0; j < 3; j++)
                        mma_tf32(&acc[(i * 3 + j) * 4], af[i], bf[j]);
            }
        } else {
#pragma unroll
            for (int k = 0; k < BKT; k++) {
                float a[8], b[4];
#pragma unroll
                for (int s = 0; s < 8; s++)
                    a[s] = __uint_as_float(As[cur][rowHalf + s * 8 + rl][k]);
#pragma unroll
                for (int j = 0; j < 4; j++)
                    b[j] = __uint_as_float(Ws[cur][colB + j][k]);
#pragma unroll
                for (int s = 0; s < 8; s++)
#pragma unroll
                    for (int j = 0; j < 4; j++)
                        acc[s * 4 + j] = fmaf(a[s], b[j], acc[s * 4 + j]);
            }
        }
        if (kt + 1 < KITERS) {
            const int nxt = (kt + 1) & 1;
            if (isT) {
                *(uint4*)&As[nxt][rowA][qd * 4]      = cvt4(ra0);
                *(uint4*)&As[nxt][rowA + 64][qd * 4] = cvt4(ra1);
            } else {
#pragma unroll
                for (int r = 0; r < 4; r++)
                    *(uint4*)&Ws[nxt][rowB + 32 * r][qdB * 4] = cvt4(rb[r]);
            }
        }
        __syncthreads();
    }
}

// ---------------------------------------------------------------------------
// Kernel 1: qkv GEMM, hybrid. grid (9 e-tiles, 784 bn-tiles), 384 threads.
// ---------------------------------------------------------------------------
__global__ __launch_bounds__(384, 2) void qkv_hyb(const float* __restrict__ x,
                                                  const float* __restrict__ w) {
    __shared__ __align__(16) uint32_t As[2][128][20];
    __shared__ __align__(16) uint32_t Ws[2][128][20];

    const int tid  = threadIdx.x;
    const int lane = tid & 31;
    const int warp = tid >> 5;
    const size_t mBase = (size_t)blockIdx.y * 128;
    const int    eBase = blockIdx.x * 128;

    float acc[48];
    hybrid_loop(x + mBase * DMODEL, w + (size_t)eBase * DMODEL,
                (SmTile*)As, (SmTile*)Ws, acc, tid);

    // epilogue: 3 rounds (48/48/32 cols) staged [col][tok] for [e][n] stores
    float (*stage)[132] = (float(*)[132])&As[0][0][0];   // 48*132*4 = 25KB
    const size_t PART = (size_t)B_SZ * DMODEL * NTOK;
    const int gid = lane >> 2, tig = lane & 3;
    const int wm = warp >> 2, wn = warp & 3;
    const int fw = warp - 8, rl = lane & 7, cg = lane >> 3;

    for (int r = 0; r < 3; r++) {
        __syncthreads();
        if (r < 2) {
            if (warp < 8 && (wn >> 1) == r) {
                int cb = (wn & 1) * 24;
#pragma unroll
                for (int i = 0; i < 4; i++) {
                    int m0 = wm * 64 + i * 16 + gid;
#pragma unroll
                    for (int j = 0; j < 3; j++) {
                        int c = cb + j * 8 + 2 * tig;
                        stage[c][m0]         = acc[(i * 3 + j) * 4 + 0];
                        stage[c + 1][m0]     = acc[(i * 3 + j) * 4 + 1];
                        stage[c][m0 + 8]     = acc[(i * 3 + j) * 4 + 2];
                        stage[c + 1][m0 + 8] = acc[(i * 3 + j) * 4 + 3];
                    }
                }
            }
        } else if (warp >= 8) {
            int cb = (fw & 1) * 16 + cg * 4;
            int rb = (fw >> 1) * 64;
#pragma unroll
            for (int s = 0; s < 8; s++)
#pragma unroll
                for (int j = 0; j < 4; j++)
                    stage[cb + j][rb + s * 8 + rl] = acc[s * 4 + j];
        }
        __syncthreads();
        const int nf4 = (r < 2) ? 1536 : 1024;
        for (int v = tid; v < nf4; v += 384) {
            int el = v >> 5;
            int n4 = (v & 31) * 4;
            int e  = eBase + r * 48 + el;
            int part = e / DMODEL, rr = e - part * DMODEL;
            size_t bn = mBase + n4;
            int b = (int)(bn / NTOK);
            int n = (int)(bn - (size_t)b * NTOK);
            *(float4*)(g_qkv + (size_t)part * PART + ((size_t)b * DMODEL + rr) * NTOK + n) =
                *(float4*)&stage[el][n4];
        }
    }
}

// ---------------------------------------------------------------------------
// Kernel 2: per-row inverse L2 norm for q and k
// ---------------------------------------------------------------------------
__global__ __launch_bounds__(256) void norm_kernel() {
    const int row  = blockIdx.x;
    const int part = row / (B_SZ * DMODEL);
    const int rr   = row % (B_SZ * DMODEL);
    const float4* p = (const float4*)(g_qkv + (size_t)part * B_SZ * DMODEL * NTOK
                                      + (size_t)rr * NTOK);
    const int tid = threadIdx.x;
    float s = 0.f;
    for (int i = tid; i < NTOK / 4; i += 256) {
        float4 v = p[i];
        s += v.x * v.x + v.y * v.y + v.z * v.z + v.w * v.w;
    }
#pragma unroll
    for (int off = 16; off; off >>= 1) s += __shfl_down_sync(0xFFFFFFFFu, s, off);
    __shared__ float ws[8];
    if ((tid & 31) == 0) ws[tid >> 5] = s;
    __syncthreads();
    if (tid == 0) {
        float t = 0.f;
#pragma unroll
        for (int i = 0; i < 8; i++) t += ws[i];
        g_rnorm[row] = 1.0f / fmaxf(sqrtf(t), 1e-12f);
    }
}

// ---------------------------------------------------------------------------
// Kernel 3a: partial QK^T: grid (7 chunks, 256 bh). Deterministic partials.
// ---------------------------------------------------------------------------
__global__ __launch_bounds__(256) void qk_partial() {
    const int chunk = blockIdx.x;
    const int bh    = blockIdx.y;
    const int b = bh >> 3, h = bh & 7;

    const size_t PART = (size_t)B_SZ * DMODEL * NTOK;
    const float* qp = g_qkv + ((size_t)b * DMODEL + h * CDIM) * NTOK;
    const float* kp = g_qkv + PART + ((size_t)b * DMODEL + h * CDIM) * NTOK;

    __shared__ float qs[48][65];
    __shared__ float ks[48][65];

    const int tid = threadIdx.x;
    const int tx = tid & 15;
    const int ty = tid >> 4;
    float acc[3][3];
#pragma unroll
    for (int i = 0; i < 3; i++)
#pragma unroll
        for (int j = 0; j < 3; j++) acc[i][j] = 0.f;

    const int nStart = chunk * 448;
    for (int n0 = nStart; n0 < nStart + 448; n0 += 64) {
        __syncthreads();
#pragma unroll
        for (int r = 0; r < 3; r++) {
            int v   = tid + r * 256;
            int row = v >> 4;
            int col = (v & 15) * 4;
            float4 tq = *(const float4*)(qp + (size_t)row * NTOK + n0 + col);
            qs[row][col + 0] = tq.x; qs[row][col + 1] = tq.y;
            qs[row][col + 2] = tq.z; qs[row][col + 3] = tq.w;
            float4 tk = *(const float4*)(kp + (size_t)row * NTOK + n0 + col);
            ks[row][col + 0] = tk.x; ks[row][col + 1] = tk.y;
            ks[row][col + 2] = tk.z; ks[row][col + 3] = tk.w;
        }
        __syncthreads();
#pragma unroll 8
        for (int kk = 0; kk < 64; kk++) {
            float a0 = qs[3 * ty + 0][kk];
            float a1 = qs[3 * ty + 1][kk];
            float a2 = qs[3 * ty + 2][kk];
            float b0 = ks[3 * tx + 0][kk];
            float b1 = ks[3 * tx + 1][kk];
            float b2 = ks[3 * tx + 2][kk];
            acc[0][0] = fmaf(a0, b0, acc[0][0]); acc[0][1] = fmaf(a0, b1, acc[0][1]); acc[0][2] = fmaf(a0, b2, acc[0][2]);
            acc[1][0] = fmaf(a1, b0, acc[1][0]); acc[1][1] = fmaf(a1, b1, acc[1][1]); acc[1][2] = fmaf(a1, b2, acc[1][2]);
            acc[2][0] = fmaf(a2, b0, acc[2][0]); acc[2][1] = fmaf(a2, b1, acc[2][1]); acc[2][2] = fmaf(a2, b2, acc[2][2]);
        }
    }

    float* dst = g_attnp + ((size_t)chunk * 256 + bh) * (CDIM * CDIM);
#pragma unroll
    for (int i = 0; i < 3; i++)
#pragma unroll
        for (int j = 0; j < 3; j++)
            dst[(3 * ty + i) * CDIM + 3 * tx + j] = acc[i][j];
}

// ---------------------------------------------------------------------------
// Kernel 3b: reduce partials, scale, row softmax
// ---------------------------------------------------------------------------
__global__ __launch_bounds__(64) void softmax_kernel(const float* __restrict__ temp) {
    const int bh = blockIdx.x;
    const int b = bh >> 3, h = bh & 7;
    const int tid = threadIdx.x;

    __shared__ float kinv[48];
    if (tid < 48) kinv[tid] = g_rnorm[B_SZ * DMODEL + b * DMODEL + h * CDIM + tid];
    __syncthreads();
    if (tid >= 48) return;

    const float qi = g_rnorm[b * DMODEL + h * CDIM + tid];
    const float tv = temp[h];
    const size_t base = (size_t)bh * (CDIM * CDIM) + (size_t)tid * CDIM;

    float r[48];
#pragma unroll
    for (int d = 0; d < 48; d++) {
        float s = 0.f;
#pragma unroll
        for (int p = 0; p < 7; p++)
            s += g_attnp[(size_t)p * 256 * CDIM * CDIM + base + d];
        r[d] = s * qi * kinv[d] * tv;
    }
    float m = -1e30f;
#pragma unroll
    for (int d = 0; d < 48; d++) m = fmaxf(m, r[d]);
    float s = 0.f;
#pragma unroll
    for (int d = 0; d < 48; d++) { r[d] = expf(r[d] - m); s += r[d]; }
    float inv = 1.0f / s;
#pragma unroll
    for (int d = 0; d < 48; d++) g_attn[base + d] = r[d] * inv;
}

// ---------------------------------------------------------------------------
// Kernel 3c: ctx = attn . v, parallel over (chunk, bh)
// ---------------------------------------------------------------------------
__global__ __launch_bounds__(256) void av_kernel() {
    const int chunk = blockIdx.x;
    const int bh    = blockIdx.y;
    const int b = bh >> 3, h = bh & 7;

    const size_t PART = (size_t)B_SZ * DMODEL * NTOK;
    const float* vp = g_qkv + 2 * PART + ((size_t)b * DMODEL + h * CDIM) * NTOK;

    __shared__ float vsm[48][65];
    __shared__ float attn[48][49];
    __shared__ float osm[48][65];

    const int tid = threadIdx.x;
    for (int v = tid; v < 48 * 48; v += 256)
        attn[v / 48][v % 48] = g_attn[(size_t)bh * CDIM * CDIM + v];

    const int tx2 = tid & 63;
    const int ty2 = tid >> 6;
    float* dstBase = g_ctx + (size_t)b * NTOK * DMODEL + h * CDIM;

    const int nStart = chunk * 448;
    for (int n0 = nStart; n0 < nStart + 448; n0 += 64) {
        __syncthreads();
#pragma unroll
        for (int r = 0; r < 3; r++) {
            int v   = tid + r * 256;
            int row = v >> 4;
            int col = (v & 15) * 4;
            float4 tv = *(const float4*)(vp + (size_t)row * NTOK + n0 + col);
            vsm[row][col + 0] = tv.x; vsm[row][col + 1] = tv.y;
            vsm[row][col + 2] = tv.z; vsm[row][col + 3] = tv.w;
        }
        __syncthreads();

        float out[12];
#pragma unroll
        for (int i = 0; i < 12; i++) out[i] = 0.f;
#pragma unroll 8
        for (int d = 0; d < 48; d++) {
            float v = vsm[d][tx2];
#pragma unroll
            for (int i = 0; i < 12; i++)
                out[i] = fmaf(attn[ty2 + 4 * i][d], v, out[i]);
        }
#pragma unroll
        for (int i = 0; i < 12; i++) osm[ty2 + 4 * i][tx2] = out[i];
        __syncthreads();
        for (int v = tid; v < 48 * 64; v += 256) {
            int c = v % 48;
            int n = v / 48;
            dstBase[(size_t)(n0 + n) * DMODEL + c] = osm[c][n];
        }
    }
}

// ---------------------------------------------------------------------------
// Kernel 4: proj GEMM, hybrid. grid (3 e-tiles, 784 bn-tiles), 384 threads.
// ---------------------------------------------------------------------------
__global__ __launch_bounds__(384, 2) void proj_hyb(const float* __restrict__ w,
                                                   const float* __restrict__ bias,
                                                   float* __restrict__ y) {
    __shared__ __align__(16) uint32_t As[2][128][20];
    __shared__ __align__(16) uint32_t Ws[2][128][20];

    const int tid  = threadIdx.x;
    const int lane = tid & 31;
    const int warp = tid >> 5;
    const size_t mBase = (size_t)blockIdx.y * 128;
    const int    eBase = blockIdx.x * 128;

    float acc[48];
    hybrid_loop(g_ctx + mBase * DMODEL, w + (size_t)eBase * DMODEL,
                (SmTile*)As, (SmTile*)Ws, acc, tid);

    // epilogue: 3 rounds staged [tok][col] (stride 52) -> row-major y + bias
    float* stg = (float*)&As[0][0][0];   // 128*52*4 = 26.6KB
    const int gid = lane >> 2, tig = lane & 3;
    const int wm = warp >> 2, wn = warp & 3;
    const int fw = warp - 8, rl = lane & 7, cg = lane >> 3;

    for (int r = 0; r < 3; r++) {
        __syncthreads();
        if (r < 2) {
            if (warp < 8 && (wn >> 1) == r) {
                int cb = (wn & 1) * 24;
#pragma unroll
                for (int i = 0; i < 4; i++) {
                    int m0 = wm * 64 + i * 16 + gid;
#pragma unroll
                    for (int j = 0; j < 3; j++) {
                        int c = cb + j * 8 + 2 * tig;
                        stg[m0 * 52 + c]           = acc[(i * 3 + j) * 4 + 0];
                        stg[m0 * 52 + c + 1]       = acc[(i * 3 + j) * 4 + 1];
                        stg[(m0 + 8) * 52 + c]     = acc[(i * 3 + j) * 4 + 2];
                        stg[(m0 + 8) * 52 + c + 1] = acc[(i * 3 + j) * 4 + 3];
                    }
                }
            }
        } else if (warp >= 8) {
            int cb = (fw & 1) * 16 + cg * 4;
            int rb = (fw >> 1) * 64;
#pragma unroll
            for (int s = 0; s < 8; s++)
#pragma unroll
                for (int j = 0; j < 4; j++)
                    stg[(rb + s * 8 + rl) * 52 + cb + j] = acc[s * 4 + j];
        }
        __syncthreads();
        if (r < 2) {
            for (int v = tid; v < 1536; v += 384) {
                int tok = v / 12, q = v - tok * 12;
                int e0 = eBase + r * 48 + q * 4;
                float4 bv = *(const float4*)(bias + e0);
                float4 o  = *(float4*)&stg[tok * 52 + q * 4];
                o.x += bv.x; o.y += bv.y; o.z += bv.z; o.w += bv.w;
                *(float4*)(y + (mBase + tok) * DMODEL + e0) = o;
            }
        } else {
            for (int v = tid; v < 1024; v += 384) {
                int tok = v >> 3, q = v & 7;
                int e0 = eBase + 96 + q * 4;
                float4 bv = *(const float4*)(bias + e0);
                float4 o  = *(float4*)&stg[tok * 52 + q * 4];
                o.x += bv.x; o.y += bv.y; o.z += bv.z; o.w += bv.w;
                *(float4*)(y + (mBase + tok) * DMODEL + e0) = o;
            }
        }
    }
}

// ---------------------------------------------------------------------------
extern "C" void kernel_launch(void* const* d_in, const int* in_sizes, int n_in,
                              void* d_out, int out_size) {
    const float* x      = (const float*)d_in[0];
    const float* qkv_w  = (const float*)d_in[1];
    const float* temp   = (const float*)d_in[2];
    const float* proj_w = (const float*)d_in[3];
    const float* proj_b = (const float*)d_in[4];
    float* y = (float*)d_out;

    qkv_hyb<<<dim3(9, 784), 384>>>(x, qkv_w);
    norm_kernel<<<2 * B_SZ * DMODEL, 256>>>();
    qk_partial<<<dim3(7, B_SZ * HEADS), 256>>>();
    softmax_kernel<<<B_SZ * HEADS, 64>>>(temp);
    av_kernel<<<dim3(7, B_SZ * HEADS), 256>>>();
    proj_hyb<<<dim3(3, 784), 384>>>(proj_w, proj_b, y);
}

// round 12
// speedup vs baseline: 2.0491x; 2.0491x over previous
#include <cuda_runtime.h>
#include <cuda_fp16.h>
#include <math.h>
#include <stdint.h>

#define B_SZ   32
#define NTOK   3136
#define DMODEL 384
#define HEADS  8
#define CDIM   48
#define BKT    16
#define KITERS (DMODEL / BKT)   // 24

// Scratch (static device globals — allocation-free rule)
__device__ float g_qkv[(size_t)3 * B_SZ * DMODEL * NTOK];   // [3][B][384][N]
__device__ float g_rnorm[2 * B_SZ * DMODEL];                // [2][B][384]
__device__ float g_ctx[(size_t)B_SZ * NTOK * DMODEL];       // [B][N][D] bn-major
__device__ float g_attnp[7 * 256 * CDIM * CDIM];            // partial QK^T sums
__device__ float g_attn[256 * CDIM * CDIM];                 // softmaxed attn

// float4 -> two packed half2 (k ascending: lo=even k, hi=odd k)
__device__ __forceinline__ uint2 cvt4h(float4 t) {
    __half2 h0 = __floats2half2_rn(t.x, t.y);
    __half2 h1 = __floats2half2_rn(t.z, t.w);
    uint2 r;
    r.x = *(uint32_t*)&h0;
    r.y = *(uint32_t*)&h1;
    return r;
}

__device__ __forceinline__ void mma_f16(float* d, const uint32_t* a, const uint32_t* b) {
    asm volatile(
        "mma.sync.aligned.m16n8k16.row.col.f32.f16.f16.f32 "
        "{%0,%1,%2,%3}, {%4,%5,%6,%7}, {%8,%9}, {%0,%1,%2,%3};\n"
        : "+f"(d[0]), "+f"(d[1]), "+f"(d[2]), "+f"(d[3])
        : "r"(a[0]), "r"(a[1]), "r"(a[2]), "r"(a[3]), "r"(b[0]), "r"(b[1]));
}

// ---------------------------------------------------------------------------
// fp16 GEMM mainloop: C[128x128] = A[128,K] . B[128,K]^T, K=384, BK=16.
// Tiles stored as packed half2: T[128 rows][8 kpairs] stride 10.
// 8 warps: wm = warp>>2 (0..1) over 64 rows, wn = warp&3 over 32 cols.
// acc[i][j][4]: i = 16-row group (4), j = 8-col group (4).
// ---------------------------------------------------------------------------
typedef uint32_t HTile[128][10];

__device__ __forceinline__ void h16_loop(
    const float* __restrict__ aB, const float* __restrict__ bB,
    HTile* As, HTile* Ws, float (&acc)[4][4][4], int tid)
{
    const int lane = tid & 31;
    const int warp = tid >> 5;
    const int gid  = lane >> 2;
    const int tig  = lane & 3;
    const int wm   = warp >> 2;
    const int wn   = warp & 3;

#pragma unroll
    for (int i = 0; i < 4; i++)
#pragma unroll
        for (int j = 0; j < 4; j++)
#pragma unroll
            for (int r = 0; r < 4; r++) acc[i][j][r] = 0.f;

    const int rowL = tid >> 2;        // 0..63
    const int quad = tid & 3;         // k-quad (4 floats)
    const float* ap0 = aB + (size_t)rowL * DMODEL + quad * 4;
    const float* ap1 = aB + (size_t)(rowL + 64) * DMODEL + quad * 4;
    const float* bp0 = bB + (size_t)rowL * DMODEL + quad * 4;
    const float* bp1 = bB + (size_t)(rowL + 64) * DMODEL + quad * 4;

    float4 va0 = *(const float4*)ap0;
    float4 va1 = *(const float4*)ap1;
    float4 vb0 = *(const float4*)bp0;
    float4 vb1 = *(const float4*)bp1;
    *(uint2*)&As[0][rowL][quad * 2]      = cvt4h(va0);
    *(uint2*)&As[0][rowL + 64][quad * 2] = cvt4h(va1);
    *(uint2*)&Ws[0][rowL][quad * 2]      = cvt4h(vb0);
    *(uint2*)&Ws[0][rowL + 64][quad * 2] = cvt4h(vb1);
    __syncthreads();

    for (int kt = 0; kt < KITERS; kt++) {
        const int cur = kt & 1;
        if (kt + 1 < KITERS) {
            const int kb = (kt + 1) * BKT;
            va0 = *(const float4*)(ap0 + kb);
            va1 = *(const float4*)(ap1 + kb);
            vb0 = *(const float4*)(bp0 + kb);
            vb1 = *(const float4*)(bp1 + kb);
        }
        uint32_t af[4][4], bf[4][2];
#pragma unroll
        for (int i = 0; i < 4; i++) {
            int m = wm * 64 + i * 16;
            af[i][0] = As[cur][m + gid][tig];
            af[i][1] = As[cur][m + gid + 8][tig];
            af[i][2] = As[cur][m + gid][tig + 4];
            af[i][3] = As[cur][m + gid + 8][tig + 4];
        }
#pragma unroll
        for (int j = 0; j < 4; j++) {
            int n = wn * 32 + j * 8;
            bf[j][0] = Ws[cur][n + gid][tig];
            bf[j][1] = Ws[cur][n + gid][tig + 4];
        }
#pragma unroll
        for (int i = 0; i < 4; i++)
#pragma unroll
            for (int j = 0; j < 4; j++)
                mma_f16(acc[i][j], af[i], bf[j]);

        if (kt + 1 < KITERS) {
            const int nxt = (kt + 1) & 1;
            *(uint2*)&As[nxt][rowL][quad * 2]      = cvt4h(va0);
            *(uint2*)&As[nxt][rowL + 64][quad * 2] = cvt4h(va1);
            *(uint2*)&Ws[nxt][rowL][quad * 2]      = cvt4h(vb0);
            *(uint2*)&Ws[nxt][rowL + 64][quad * 2] = cvt4h(vb1);
        }
        __syncthreads();
    }
}

// ---------------------------------------------------------------------------
// Kernel 1: qkv GEMM (fp16 mma). grid (9 e-tiles, 784 bn-tiles).
// ---------------------------------------------------------------------------
__global__ __launch_bounds__(256) void qkv_h16(const float* __restrict__ x,
                                               const float* __restrict__ w) {
    __shared__ __align__(16) uint32_t As[2][128][10];
    __shared__ __align__(16) uint32_t Ws[2][128][10];
    __shared__ __align__(16) float stage[32][132];

    const int tid  = threadIdx.x;
    const int lane = tid & 31;
    const int warp = tid >> 5;
    const int gid = lane >> 2, tig = lane & 3;
    const int wm = warp >> 2, wn = warp & 3;

    const size_t mBase = (size_t)blockIdx.y * 128;
    const int    eBase = blockIdx.x * 128;

    float acc[4][4][4];
    h16_loop(x + mBase * DMODEL, w + (size_t)eBase * DMODEL,
             (HTile*)As, (HTile*)Ws, acc, tid);

    // epilogue: 4 rounds of 32 e-cols, staged [e][tok] for coalesced [e][n] stores
    const size_t PART = (size_t)B_SZ * DMODEL * NTOK;
    for (int rnd = 0; rnd < 4; rnd++) {
        __syncthreads();
        if (wn == rnd) {
#pragma unroll
            for (int i = 0; i < 4; i++) {
                int m0 = wm * 64 + i * 16 + gid;
#pragma unroll
                for (int j = 0; j < 4; j++) {
                    int e0 = j * 8 + 2 * tig;
                    stage[e0][m0]         = acc[i][j][0];
                    stage[e0 + 1][m0]     = acc[i][j][1];
                    stage[e0][m0 + 8]     = acc[i][j][2];
                    stage[e0 + 1][m0 + 8] = acc[i][j][3];
                }
            }
        }
        __syncthreads();
        int tok4 = (tid & 31) * 4;
#pragma unroll
        for (int ii = 0; ii < 4; ii++) {
            int el = (tid >> 5) + 8 * ii;
            int eg = eBase + rnd * 32 + el;
            int part = eg / DMODEL, rr = eg % DMODEL;
            size_t bn = mBase + tok4;
            int b = (int)(bn / NTOK);
            int n = (int)(bn - (size_t)b * NTOK);
            *(float4*)(g_qkv + (size_t)part * PART + ((size_t)b * DMODEL + rr) * NTOK + n) =
                *(float4*)&stage[el][tok4];
        }
    }
}

// ---------------------------------------------------------------------------
// Kernel 2: per-row inverse L2 norm for q and k
// ---------------------------------------------------------------------------
__global__ __launch_bounds__(256) void norm_kernel() {
    const int row  = blockIdx.x;
    const int part = row / (B_SZ * DMODEL);
    const int rr   = row % (B_SZ * DMODEL);
    const float4* p = (const float4*)(g_qkv + (size_t)part * B_SZ * DMODEL * NTOK
                                      + (size_t)rr * NTOK);
    const int tid = threadIdx.x;
    float s = 0.f;
    for (int i = tid; i < NTOK / 4; i += 256) {
        float4 v = p[i];
        s += v.x * v.x + v.y * v.y + v.z * v.z + v.w * v.w;
    }
#pragma unroll
    for (int off = 16; off; off >>= 1) s += __shfl_down_sync(0xFFFFFFFFu, s, off);
    __shared__ float ws[8];
    if ((tid & 31) == 0) ws[tid >> 5] = s;
    __syncthreads();
    if (tid == 0) {
        float t = 0.f;
#pragma unroll
        for (int i = 0; i < 8; i++) t += ws[i];
        g_rnorm[row] = 1.0f / fmaxf(sqrtf(t), 1e-12f);
    }
}

// ---------------------------------------------------------------------------
// Kernel 3a: partial QK^T: grid (7 chunks, 256 bh). Deterministic partials.
// ---------------------------------------------------------------------------
__global__ __launch_bounds__(256) void qk_partial() {
    const int chunk = blockIdx.x;
    const int bh    = blockIdx.y;
    const int b = bh >> 3, h = bh & 7;

    const size_t PART = (size_t)B_SZ * DMODEL * NTOK;
    const float* qp = g_qkv + ((size_t)b * DMODEL + h * CDIM) * NTOK;
    const float* kp = g_qkv + PART + ((size_t)b * DMODEL + h * CDIM) * NTOK;

    __shared__ float qs[48][65];
    __shared__ float ks[48][65];

    const int tid = threadIdx.x;
    const int tx = tid & 15;
    const int ty = tid >> 4;
    float acc[3][3];
#pragma unroll
    for (int i = 0; i < 3; i++)
#pragma unroll
        for (int j = 0; j < 3; j++) acc[i][j] = 0.f;

    const int nStart = chunk * 448;
    for (int n0 = nStart; n0 < nStart + 448; n0 += 64) {
        __syncthreads();
#pragma unroll
        for (int r = 0; r < 3; r++) {
            int v   = tid + r * 256;
            int row = v >> 4;
            int col = (v & 15) * 4;
            float4 tq = *(const float4*)(qp + (size_t)row * NTOK + n0 + col);
            qs[row][col + 0] = tq.x; qs[row][col + 1] = tq.y;
            qs[row][col + 2] = tq.z; qs[row][col + 3] = tq.w;
            float4 tk = *(const float4*)(kp + (size_t)row * NTOK + n0 + col);
            ks[row][col + 0] = tk.x; ks[row][col + 1] = tk.y;
            ks[row][col + 2] = tk.z; ks[row][col + 3] = tk.w;
        }
        __syncthreads();
#pragma unroll 8
        for (int kk = 0; kk < 64; kk++) {
            float a0 = qs[3 * ty + 0][kk];
            float a1 = qs[3 * ty + 1][kk];
            float a2 = qs[3 * ty + 2][kk];
            float b0 = ks[3 * tx + 0][kk];
            float b1 = ks[3 * tx + 1][kk];
            float b2 = ks[3 * tx + 2][kk];
            acc[0][0] = fmaf(a0, b0, acc[0][0]); acc[0][1] = fmaf(a0, b1, acc[0][1]); acc[0][2] = fmaf(a0, b2, acc[0][2]);
            acc[1][0] = fmaf(a1, b0, acc[1][0]); acc[1][1] = fmaf(a1, b1, acc[1][1]); acc[1][2] = fmaf(a1, b2, acc[1][2]);
            acc[2][0] = fmaf(a2, b0, acc[2][0]); acc[2][1] = fmaf(a2, b1, acc[2][1]); acc[2][2] = fmaf(a2, b2, acc[2][2]);
        }
    }

    float* dst = g_attnp + ((size_t)chunk * 256 + bh) * (CDIM * CDIM);
#pragma unroll
    for (int i = 0; i < 3; i++)
#pragma unroll
        for (int j = 0; j < 3; j++)
            dst[(3 * ty + i) * CDIM + 3 * tx + j] = acc[i][j];
}

// ---------------------------------------------------------------------------
// Kernel 3b: reduce partials, scale, row softmax
// ---------------------------------------------------------------------------
__global__ __launch_bounds__(64) void softmax_kernel(const float* __restrict__ temp) {
    const int bh = blockIdx.x;
    const int b = bh >> 3, h = bh & 7;
    const int tid = threadIdx.x;

    __shared__ float kinv[48];
    if (tid < 48) kinv[tid] = g_rnorm[B_SZ * DMODEL + b * DMODEL + h * CDIM + tid];
    __syncthreads();
    if (tid >= 48) return;

    const float qi = g_rnorm[b * DMODEL + h * CDIM + tid];
    const float tv = temp[h];
    const size_t base = (size_t)bh * (CDIM * CDIM) + (size_t)tid * CDIM;

    float r[48];
#pragma unroll
    for (int d = 0; d < 48; d++) {
        float s = 0.f;
#pragma unroll
        for (int p = 0; p < 7; p++)
            s += g_attnp[(size_t)p * 256 * CDIM * CDIM + base + d];
        r[d] = s * qi * kinv[d] * tv;
    }
    float m = -1e30f;
#pragma unroll
    for (int d = 0; d < 48; d++) m = fmaxf(m, r[d]);
    float s = 0.f;
#pragma unroll
    for (int d = 0; d < 48; d++) { r[d] = expf(r[d] - m); s += r[d]; }
    float inv = 1.0f / s;
#pragma unroll
    for (int d = 0; d < 48; d++) g_attn[base + d] = r[d] * inv;
}

// ---------------------------------------------------------------------------
// Kernel 3c: ctx = attn . v, parallel over (chunk, bh)
// ---------------------------------------------------------------------------
__global__ __launch_bounds__(256) void av_kernel() {
    const int chunk = blockIdx.x;
    const int bh    = blockIdx.y;
    const int b = bh >> 3, h = bh & 7;

    const size_t PART = (size_t)B_SZ * DMODEL * NTOK;
    const float* vp = g_qkv + 2 * PART + ((size_t)b * DMODEL + h * CDIM) * NTOK;

    __shared__ float vsm[48][65];
    __shared__ float attn[48][49];
    __shared__ float osm[48][65];

    const int tid = threadIdx.x;
    for (int v = tid; v < 48 * 48; v += 256)
        attn[v / 48][v % 48] = g_attn[(size_t)bh * CDIM * CDIM + v];

    const int tx2 = tid & 63;
    const int ty2 = tid >> 6;
    float* dstBase = g_ctx + (size_t)b * NTOK * DMODEL + h * CDIM;

    const int nStart = chunk * 448;
    for (int n0 = nStart; n0 < nStart + 448; n0 += 64) {
        __syncthreads();
#pragma unroll
        for (int r = 0; r < 3; r++) {
            int v   = tid + r * 256;
            int row = v >> 4;
            int col = (v & 15) * 4;
            float4 tv = *(const float4*)(vp + (size_t)row * NTOK + n0 + col);
            vsm[row][col + 0] = tv.x; vsm[row][col + 1] = tv.y;
            vsm[row][col + 2] = tv.z; vsm[row][col + 3] = tv.w;
        }
        __syncthreads();

        float out[12];
#pragma unroll
        for (int i = 0; i < 12; i++) out[i] = 0.f;
#pragma unroll 8
        for (int d = 0; d < 48; d++) {
            float v = vsm[d][tx2];
#pragma unroll
            for (int i = 0; i < 12; i++)
                out[i] = fmaf(attn[ty2 + 4 * i][d], v, out[i]);
        }
#pragma unroll
        for (int i = 0; i < 12; i++) osm[ty2 + 4 * i][tx2] = out[i];
        __syncthreads();
        for (int v = tid; v < 48 * 64; v += 256) {
            int c = v % 48;
            int n = v / 48;
            dstBase[(size_t)(n0 + n) * DMODEL + c] = osm[c][n];
        }
    }
}

// ---------------------------------------------------------------------------
// Kernel 4: proj GEMM (fp16 mma). grid (3 e-tiles, 784 bn-tiles).
// ---------------------------------------------------------------------------
__global__ __launch_bounds__(256) void proj_h16(const float* __restrict__ w,
                                                const float* __restrict__ bias,
                                                float* __restrict__ y) {
    __shared__ __align__(16) uint32_t As[2][128][10];
    __shared__ __align__(16) uint32_t Ws[2][128][10];

    const int tid  = threadIdx.x;
    const int lane = tid & 31;
    const int warp = tid >> 5;
    const int gid = lane >> 2, tig = lane & 3;
    const int wm = warp >> 2, wn = warp & 3;

    const size_t mBase = (size_t)blockIdx.y * 128;
    const int    eBase = blockIdx.x * 128;

    float acc[4][4][4];
    h16_loop(g_ctx + mBase * DMODEL, w + (size_t)eBase * DMODEL,
             (HTile*)As, (HTile*)Ws, acc, tid);

#pragma unroll
    for (int i = 0; i < 4; i++) {
        size_t bn0 = mBase + wm * 64 + i * 16 + gid;
#pragma unroll
        for (int j = 0; j < 4; j++) {
            int e = eBase + wn * 32 + j * 8 + 2 * tig;
            float2 b2 = *(const float2*)(bias + e);
            float2 o0 = make_float2(acc[i][j][0] + b2.x, acc[i][j][1] + b2.y);
            float2 o1 = make_float2(acc[i][j][2] + b2.x, acc[i][j][3] + b2.y);
            *(float2*)(y + bn0 * DMODEL + e)       = o0;
            *(float2*)(y + (bn0 + 8) * DMODEL + e) = o1;
        }
    }
}

// ---------------------------------------------------------------------------
extern "C" void kernel_launch(void* const* d_in, const int* in_sizes, int n_in,
                              void* d_out, int out_size) {
    const float* x      = (const float*)d_in[0];
    const float* qkv_w  = (const float*)d_in[1];
    const float* temp   = (const float*)d_in[2];
    const float* proj_w = (const float*)d_in[3];
    const float* proj_b = (const float*)d_in[4];
    float* y = (float*)d_out;

    qkv_h16<<<dim3(9, 784), 256>>>(x, qkv_w);
    norm_kernel<<<2 * B_SZ * DMODEL, 256>>>();
    qk_partial<<<dim3(7, B_SZ * HEADS), 256>>>();
    softmax_kernel<<<B_SZ * HEADS, 64>>>(temp);
    av_kernel<<<dim3(7, B_SZ * HEADS), 256>>>();
    proj_h16<<<dim3(3, 784), 256>>>(proj_w, proj_b, y);
}

// round 14
// speedup vs baseline: 2.5251x; 1.2323x over previous
#include <cuda_runtime.h>
#include <cuda_fp16.h>
#include <math.h>
#include <stdint.h>

#define B_SZ   32
#define NTOK   3136
#define DMODEL 384
#define HEADS  8
#define CDIM   48
#define BKT    16
#define KITERS (DMODEL / BKT)   // 24

// Scratch (static device globals — allocation-free rule)
__device__ float g_qkv[(size_t)3 * B_SZ * DMODEL * NTOK];   // [3][B][384][N]
__device__ float g_ctx[(size_t)B_SZ * NTOK * DMODEL];       // [B][N][D] bn-major
__device__ float g_attnp[7 * 256 * CDIM * CDIM];            // partial QK^T sums
__device__ float g_normp[7 * 256 * 96];                     // partial sumsq (48 q + 48 k)
__device__ float g_attn[256 * CDIM * CDIM];                 // softmaxed attn

// float4 -> two packed half2 (k ascending)
__device__ __forceinline__ uint2 cvt4h(float4 t) {
    __half2 h0 = __floats2half2_rn(t.x, t.y);
    __half2 h1 = __floats2half2_rn(t.z, t.w);
    uint2 r;
    r.x = *(uint32_t*)&h0;
    r.y = *(uint32_t*)&h1;
    return r;
}

__device__ __forceinline__ void mma_f16(float* d, const uint32_t* a, const uint32_t* b) {
    asm volatile(
        "mma.sync.aligned.m16n8k16.row.col.f32.f16.f16.f32 "
        "{%0,%1,%2,%3}, {%4,%5,%6,%7}, {%8,%9}, {%0,%1,%2,%3};\n"
        : "+f"(d[0]), "+f"(d[1]), "+f"(d[2]), "+f"(d[3])
        : "r"(a[0]), "r"(a[1]), "r"(a[2]), "r"(a[3]), "r"(b[0]), "r"(b[1]));
}
__device__ __forceinline__ void ldsm_x4(uint32_t* r, uint32_t addr) {
    asm volatile("ldmatrix.sync.aligned.m8n8.x4.shared.b16 {%0,%1,%2,%3}, [%4];"
        : "=r"(r[0]), "=r"(r[1]), "=r"(r[2]), "=r"(r[3]) : "r"(addr));
}
__device__ __forceinline__ void ldsm_x2(uint32_t* r, uint32_t addr) {
    asm volatile("ldmatrix.sync.aligned.m8n8.x2.shared.b16 {%0,%1}, [%2];"
        : "=r"(r[0]), "=r"(r[1]) : "r"(addr));
}

// ---------------------------------------------------------------------------
// fp16 GEMM mainloop with ldmatrix: C[128x128] = A[128,K] . B[128,K]^T.
// Tiles: [128 rows][12 words] (8 data words = 16 halves, 4 pad). 48B row stride
// keeps all ldmatrix 8-row phases on distinct 16B quad-banks.
// ---------------------------------------------------------------------------
typedef uint32_t HTile[128][12];

__device__ __forceinline__ void h16_loop(
    const float* __restrict__ aB, const float* __restrict__ bB,
    HTile* As, HTile* Ws, float (&acc)[4][4][4], int tid)
{
    const int lane = tid & 31;
    const int warp = tid >> 5;
    const int wm   = warp >> 2;
    const int wn   = warp & 3;

#pragma unroll
    for (int i = 0; i < 4; i++)
#pragma unroll
        for (int j = 0; j < 4; j++)
#pragma unroll
            for (int r = 0; r < 4; r++) acc[i][j][r] = 0.f;

    const int rowL = tid >> 2;        // 0..63
    const int quad = tid & 3;
    const float* ap0 = aB + (size_t)rowL * DMODEL + quad * 4;
    const float* ap1 = aB + (size_t)(rowL + 64) * DMODEL + quad * 4;
    const float* bp0 = bB + (size_t)rowL * DMODEL + quad * 4;
    const float* bp1 = bB + (size_t)(rowL + 64) * DMODEL + quad * 4;

    // ldmatrix lane address offsets (bytes)
    const uint32_t aLane = ((uint32_t)(wm * 64 + (lane & 7) + ((lane >> 3) & 1) * 8) * 12
                           + ((lane >> 4) & 1) * 4) * 4;
    const uint32_t bLane = ((uint32_t)(lane & 7) * 12 + ((lane >> 3) & 1) * 4) * 4;
    const uint32_t sA0 = (uint32_t)__cvta_generic_to_shared(&As[0][0][0]);
    const uint32_t sA1 = (uint32_t)__cvta_generic_to_shared(&As[1][0][0]);
    const uint32_t sW0 = (uint32_t)__cvta_generic_to_shared(&Ws[0][0][0]);
    const uint32_t sW1 = (uint32_t)__cvta_generic_to_shared(&Ws[1][0][0]);

    float4 va0 = *(const float4*)ap0;
    float4 va1 = *(const float4*)ap1;
    float4 vb0 = *(const float4*)bp0;
    float4 vb1 = *(const float4*)bp1;
    *(uint2*)&As[0][rowL][quad * 2]      = cvt4h(va0);
    *(uint2*)&As[0][rowL + 64][quad * 2] = cvt4h(va1);
    *(uint2*)&Ws[0][rowL][quad * 2]      = cvt4h(vb0);
    *(uint2*)&Ws[0][rowL + 64][quad * 2] = cvt4h(vb1);
    __syncthreads();

    for (int kt = 0; kt < KITERS; kt++) {
        const int cur = kt & 1;
        if (kt + 1 < KITERS) {
            const int kb = (kt + 1) * BKT;
            va0 = *(const float4*)(ap0 + kb);
            va1 = *(const float4*)(ap1 + kb);
            vb0 = *(const float4*)(bp0 + kb);
            vb1 = *(const float4*)(bp1 + kb);
        }
        const uint32_t sa = (cur ? sA1 : sA0) + aLane;
        const uint32_t sw = (cur ? sW1 : sW0) + bLane;
        uint32_t af[4][4], bf[4][2];
#pragma unroll
        for (int i = 0; i < 4; i++) ldsm_x4(af[i], sa + (uint32_t)(i * 16 * 48));
#pragma unroll
        for (int j = 0; j < 4; j++) ldsm_x2(bf[j], sw + (uint32_t)((wn * 32 + j * 8) * 48));
#pragma unroll
        for (int i = 0; i < 4; i++)
#pragma unroll
            for (int j = 0; j < 4; j++)
                mma_f16(acc[i][j], af[i], bf[j]);

        if (kt + 1 < KITERS) {
            const int nxt = (kt + 1) & 1;
            *(uint2*)&As[nxt][rowL][quad * 2]      = cvt4h(va0);
            *(uint2*)&As[nxt][rowL + 64][quad * 2] = cvt4h(va1);
            *(uint2*)&Ws[nxt][rowL][quad * 2]      = cvt4h(vb0);
            *(uint2*)&Ws[nxt][rowL + 64][quad * 2] = cvt4h(vb1);
        }
        __syncthreads();
    }
}

// ---------------------------------------------------------------------------
// Kernel 1: qkv GEMM (fp16 mma + ldmatrix). grid (9 e-tiles, 784 bn-tiles).
// ---------------------------------------------------------------------------
__global__ __launch_bounds__(256) void qkv_h16(const float* __restrict__ x,
                                               const float* __restrict__ w) {
    __shared__ __align__(16) uint32_t As[2][128][12];
    __shared__ __align__(16) uint32_t Ws[2][128][12];
    __shared__ __align__(16) float stage[32][132];

    const int tid  = threadIdx.x;
    const int lane = tid & 31;
    const int warp = tid >> 5;
    const int gid = lane >> 2, tig = lane & 3;
    const int wm = warp >> 2, wn = warp & 3;

    const size_t mBase = (size_t)blockIdx.y * 128;
    const int    eBase = blockIdx.x * 128;

    float acc[4][4][4];
    h16_loop(x + mBase * DMODEL, w + (size_t)eBase * DMODEL,
             (HTile*)As, (HTile*)Ws, acc, tid);

    const size_t PART = (size_t)B_SZ * DMODEL * NTOK;
    for (int rnd = 0; rnd < 4; rnd++) {
        __syncthreads();
        if (wn == rnd) {
#pragma unroll
            for (int i = 0; i < 4; i++) {
                int m0 = wm * 64 + i * 16 + gid;
#pragma unroll
                for (int j = 0; j < 4; j++) {
                    int e0 = j * 8 + 2 * tig;
                    stage[e0][m0]         = acc[i][j][0];
                    stage[e0 + 1][m0]     = acc[i][j][1];
                    stage[e0][m0 + 8]     = acc[i][j][2];
                    stage[e0 + 1][m0 + 8] = acc[i][j][3];
                }
            }
        }
        __syncthreads();
        int tok4 = (tid & 31) * 4;
#pragma unroll
        for (int ii = 0; ii < 4; ii++) {
            int el = (tid >> 5) + 8 * ii;
            int eg = eBase + rnd * 32 + el;
            int part = eg / DMODEL, rr = eg % DMODEL;
            size_t bn = mBase + tok4;
            int b = (int)(bn / NTOK);
            int n = (int)(bn - (size_t)b * NTOK);
            *(float4*)(g_qkv + (size_t)part * PART + ((size_t)b * DMODEL + rr) * NTOK + n) =
                *(float4*)&stage[el][tok4];
        }
    }
}

// ---------------------------------------------------------------------------
// Kernel 3a: partial QK^T + fused sumsq partials. grid (7 chunks, 256 bh).
// ---------------------------------------------------------------------------
__global__ __launch_bounds__(256) void qk_partial() {
    const int chunk = blockIdx.x;
    const int bh    = blockIdx.y;
    const int b = bh >> 3, h = bh & 7;

    const size_t PART = (size_t)B_SZ * DMODEL * NTOK;
    const float* qp = g_qkv + ((size_t)b * DMODEL + h * CDIM) * NTOK;
    const float* kp = g_qkv + PART + ((size_t)b * DMODEL + h * CDIM) * NTOK;

    __shared__ float qs[48][65];
    __shared__ float ks[48][65];
    __shared__ float red[96][17];

    const int tid = threadIdx.x;
    const int tx = tid & 15;
    const int ty = tid >> 4;
    float acc[3][3];
    float sq[3] = {0.f, 0.f, 0.f}, sk[3] = {0.f, 0.f, 0.f};
#pragma unroll
    for (int i = 0; i < 3; i++)
#pragma unroll
        for (int j = 0; j < 3; j++) acc[i][j] = 0.f;

    const int nStart = chunk * 448;
    for (int n0 = nStart; n0 < nStart + 448; n0 += 64) {
        __syncthreads();
#pragma unroll
        for (int r = 0; r < 3; r++) {
            int v   = tid + r * 256;
            int row = v >> 4;
            int col = (v & 15) * 4;
            float4 tq = *(const float4*)(qp + (size_t)row * NTOK + n0 + col);
            qs[row][col + 0] = tq.x; qs[row][col + 1] = tq.y;
            qs[row][col + 2] = tq.z; qs[row][col + 3] = tq.w;
            sq[r] += tq.x * tq.x + tq.y * tq.y + tq.z * tq.z + tq.w * tq.w;
            float4 tk = *(const float4*)(kp + (size_t)row * NTOK + n0 + col);
            ks[row][col + 0] = tk.x; ks[row][col + 1] = tk.y;
            ks[row][col + 2] = tk.z; ks[row][col + 3] = tk.w;
            sk[r] += tk.x * tk.x + tk.y * tk.y + tk.z * tk.z + tk.w * tk.w;
        }
        __syncthreads();
#pragma unroll 8
        for (int kk = 0; kk < 64; kk++) {
            float a0 = qs[3 * ty + 0][kk];
            float a1 = qs[3 * ty + 1][kk];
            float a2 = qs[3 * ty + 2][kk];
            float b0 = ks[3 * tx + 0][kk];
            float b1 = ks[3 * tx + 1][kk];
            float b2 = ks[3 * tx + 2][kk];
            acc[0][0] = fmaf(a0, b0, acc[0][0]); acc[0][1] = fmaf(a0, b1, acc[0][1]); acc[0][2] = fmaf(a0, b2, acc[0][2]);
            acc[1][0] = fmaf(a1, b0, acc[1][0]); acc[1][1] = fmaf(a1, b1, acc[1][1]); acc[1][2] = fmaf(a1, b2, acc[1][2]);
            acc[2][0] = fmaf(a2, b0, acc[2][0]); acc[2][1] = fmaf(a2, b1, acc[2][1]); acc[2][2] = fmaf(a2, b2, acc[2][2]);
        }
    }

    float* dst = g_attnp + ((size_t)chunk * 256 + bh) * (CDIM * CDIM);
#pragma unroll
    for (int i = 0; i < 3; i++)
#pragma unroll
        for (int j = 0; j < 3; j++)
            dst[(3 * ty + i) * CDIM + 3 * tx + j] = acc[i][j];

    // sumsq reduction: thread t owns rows (t>>4)+16r for r=0..2
    __syncthreads();
#pragma unroll
    for (int r = 0; r < 3; r++) {
        red[(tid >> 4) + 16 * r][tid & 15]      = sq[r];
        red[48 + (tid >> 4) + 16 * r][tid & 15] = sk[r];
    }
    __syncthreads();
    if (tid < 96) {
        float s = 0.f;
#pragma unroll
        for (int c = 0; c < 16; c++) s += red[tid][c];
        g_normp[((size_t)chunk * 256 + bh) * 96 + tid] = s;
    }
}

// ---------------------------------------------------------------------------
// Kernel 3b: reduce partials (attn + norms), scale, row softmax. 96 threads.
// ---------------------------------------------------------------------------
__global__ __launch_bounds__(96) void softmax_kernel(const float* __restrict__ temp) {
    const int bh = blockIdx.x;
    const int h = bh & 7;
    const int tid = threadIdx.x;

    __shared__ float kinv[48];

    // inverse norms from fused partials
    float sn = 0.f;
#pragma unroll
    for (int p = 0; p < 7; p++)
        sn += g_normp[(size_t)p * 256 * 96 + (size_t)bh * 96 + tid];
    float inv_n = 1.0f / fmaxf(sqrtf(sn), 1e-12f);
    if (tid >= 48) kinv[tid - 48] = inv_n;
    __syncthreads();
    if (tid >= 48) return;

    const float qi = inv_n;
    const float tv = temp[h];
    const size_t base = (size_t)bh * (CDIM * CDIM) + (size_t)tid * CDIM;

    float r[48];
#pragma unroll
    for (int d = 0; d < 48; d++) {
        float s = 0.f;
#pragma unroll
        for (int p = 0; p < 7; p++)
            s += g_attnp[(size_t)p * 256 * CDIM * CDIM + base + d];
        r[d] = s * qi * kinv[d] * tv;
    }
    float m = -1e30f;
#pragma unroll
    for (int d = 0; d < 48; d++) m = fmaxf(m, r[d]);
    float s = 0.f;
#pragma unroll
    for (int d = 0; d < 48; d++) { r[d] = expf(r[d] - m); s += r[d]; }
    float inv = 1.0f / s;
#pragma unroll
    for (int d = 0; d < 48; d++) g_attn[base + d] = r[d] * inv;
}

// ---------------------------------------------------------------------------
// Kernel 3c: ctx = attn . v, parallel over (chunk, bh)
// ---------------------------------------------------------------------------
__global__ __launch_bounds__(256) void av_kernel() {
    const int chunk = blockIdx.x;
    const int bh    = blockIdx.y;
    const int b = bh >> 3, h = bh & 7;

    const size_t PART = (size_t)B_SZ * DMODEL * NTOK;
    const float* vp = g_qkv + 2 * PART + ((size_t)b * DMODEL + h * CDIM) * NTOK;

    __shared__ float vsm[48][65];
    __shared__ float attn[48][49];
    __shared__ float osm[48][65];

    const int tid = threadIdx.x;
    for (int v = tid; v < 48 * 48; v += 256)
        attn[v / 48][v % 48] = g_attn[(size_t)bh * CDIM * CDIM + v];

    const int tx2 = tid & 63;
    const int ty2 = tid >> 6;
    float* dstBase = g_ctx + (size_t)b * NTOK * DMODEL + h * CDIM;

    const int nStart = chunk * 448;
    for (int n0 = nStart; n0 < nStart + 448; n0 += 64) {
        __syncthreads();
#pragma unroll
        for (int r = 0; r < 3; r++) {
            int v   = tid + r * 256;
            int row = v >> 4;
            int col = (v & 15) * 4;
            float4 tv = *(const float4*)(vp + (size_t)row * NTOK + n0 + col);
            vsm[row][col + 0] = tv.x; vsm[row][col + 1] = tv.y;
            vsm[row][col + 2] = tv.z; vsm[row][col + 3] = tv.w;
        }
        __syncthreads();

        float out[12];
#pragma unroll
        for (int i = 0; i < 12; i++) out[i] = 0.f;
#pragma unroll 8
        for (int d = 0; d < 48; d++) {
            float v = vsm[d][tx2];
#pragma unroll
            for (int i = 0; i < 12; i++)
                out[i] = fmaf(attn[ty2 + 4 * i][d], v, out[i]);
        }
#pragma unroll
        for (int i = 0; i < 12; i++) osm[ty2 + 4 * i][tx2] = out[i];
        __syncthreads();
        for (int v = tid; v < 48 * 64; v += 256) {
            int c = v % 48;
            int n = v / 48;
            dstBase[(size_t)(n0 + n) * DMODEL + c] = osm[c][n];
        }
    }
}

// ---------------------------------------------------------------------------
// Kernel 4: proj GEMM (fp16 mma + ldmatrix). grid (3 e-tiles, 784 bn-tiles).
// ---------------------------------------------------------------------------
__global__ __launch_bounds__(256) void proj_h16(const float* __restrict__ w,
                                                const float* __restrict__ bias,
                                                float* __restrict__ y) {
    __shared__ __align__(16) uint32_t As[2][128][12];
    __shared__ __align__(16) uint32_t Ws[2][128][12];

    const int tid  = threadIdx.x;
    const int lane = tid & 31;
    const int warp = tid >> 5;
    const int gid = lane >> 2, tig = lane & 3;
    const int wm = warp >> 2, wn = warp & 3;

    const size_t mBase = (size_t)blockIdx.y * 128;
    const int    eBase = blockIdx.x * 128;

    float acc[4][4][4];
    h16_loop(g_ctx + mBase * DMODEL, w + (size_t)eBase * DMODEL,
             (HTile*)As, (HTile*)Ws, acc, tid);

#pragma unroll
    for (int i = 0; i < 4; i++) {
        size_t bn0 = mBase + wm * 64 + i * 16 + gid;
#pragma unroll
        for (int j = 0; j < 4; j++) {
            int e = eBase + wn * 32 + j * 8 + 2 * tig;
            float2 b2 = *(const float2*)(bias + e);
            float2 o0 = make_float2(acc[i][j][0] + b2.x, acc[i][j][1] + b2.y);
            float2 o1 = make_float2(acc[i][j][2] + b2.x, acc[i][j][3] + b2.y);
            *(float2*)(y + bn0 * DMODEL + e)       = o0;
            *(float2*)(y + (bn0 + 8) * DMODEL + e) = o1;
        }
    }
}

// ---------------------------------------------------------------------------
extern "C" void kernel_launch(void* const* d_in, const int* in_sizes, int n_in,
                              void* d_out, int out_size) {
    const float* x      = (const float*)d_in[0];
    const float* qkv_w  = (const float*)d_in[1];
    const float* temp   = (const float*)d_in[2];
    const float* proj_w = (const float*)d_in[3];
    const float* proj_b = (const float*)d_in[4];
    float* y = (float*)d_out;

    qkv_h16<<<dim3(9, 784), 256>>>(x, qkv_w);
    qk_partial<<<dim3(7, B_SZ * HEADS), 256>>>();
    softmax_kernel<<<B_SZ * HEADS, 96>>>(temp);
    av_kernel<<<dim3(7, B_SZ * HEADS), 256>>>();
    proj_h16<<<dim3(3, 784), 256>>>(proj_w, proj_b, y);
}

// round 15
// speedup vs baseline: 3.1822x; 1.2602x over previous
#include <cuda_runtime.h>
#include <cuda_fp16.h>
#include <math.h>
#include <stdint.h>

#define B_SZ   32
#define NTOK   3136
#define DMODEL 384
#define HEADS  8
#define CDIM   48
#define BKT    16
#define KITERS (DMODEL / BKT)   // 24

// Scratch (static device globals — allocation-free rule)
__device__ float g_qkv[(size_t)2 * B_SZ * DMODEL * NTOK];          // q,k: [2][B][384][N]
__device__ float g_qkvV[((size_t)B_SZ * NTOK + 128) * DMODEL];     // v: [bn][384] (+pad)
__device__ float g_attnp[7 * 256 * CDIM * CDIM];                   // partial QK^T sums
__device__ float g_normp[7 * 256 * 96];                            // partial sumsq
__device__ float g_attn[256 * CDIM * CDIM];                        // softmaxed attn
__device__ float g_weff[(size_t)B_SZ * DMODEL * DMODEL];           // folded proj weights

// float4 -> two packed half2 (k ascending)
__device__ __forceinline__ uint2 cvt4h(float4 t) {
    __half2 h0 = __floats2half2_rn(t.x, t.y);
    __half2 h1 = __floats2half2_rn(t.z, t.w);
    uint2 r;
    r.x = *(uint32_t*)&h0;
    r.y = *(uint32_t*)&h1;
    return r;
}

__device__ __forceinline__ void mma_f16(float* d, const uint32_t* a, const uint32_t* b) {
    asm volatile(
        "mma.sync.aligned.m16n8k16.row.col.f32.f16.f16.f32 "
        "{%0,%1,%2,%3}, {%4,%5,%6,%7}, {%8,%9}, {%0,%1,%2,%3};\n"
        : "+f"(d[0]), "+f"(d[1]), "+f"(d[2]), "+f"(d[3])
        : "r"(a[0]), "r"(a[1]), "r"(a[2]), "r"(a[3]), "r"(b[0]), "r"(b[1]));
}
__device__ __forceinline__ void ldsm_x4(uint32_t* r, uint32_t addr) {
    asm volatile("ldmatrix.sync.aligned.m8n8.x4.shared.b16 {%0,%1,%2,%3}, [%4];"
        : "=r"(r[0]), "=r"(r[1]), "=r"(r[2]), "=r"(r[3]) : "r"(addr));
}
__device__ __forceinline__ void ldsm_x2(uint32_t* r, uint32_t addr) {
    asm volatile("ldmatrix.sync.aligned.m8n8.x2.shared.b16 {%0,%1}, [%2];"
        : "=r"(r[0]), "=r"(r[1]) : "r"(addr));
}

// ---------------------------------------------------------------------------
// fp16 GEMM mainloop with ldmatrix: C[128x128] = A[128,K] . B[128,K]^T.
// ---------------------------------------------------------------------------
typedef uint32_t HTile[128][12];

__device__ __forceinline__ void h16_loop(
    const float* __restrict__ aB, const float* __restrict__ bB,
    HTile* As, HTile* Ws, float (&acc)[4][4][4], int tid)
{
    const int lane = tid & 31;
    const int warp = tid >> 5;
    const int wm   = warp >> 2;
    const int wn   = warp & 3;

#pragma unroll
    for (int i = 0; i < 4; i++)
#pragma unroll
        for (int j = 0; j < 4; j++)
#pragma unroll
            for (int r = 0; r < 4; r++) acc[i][j][r] = 0.f;

    const int rowL = tid >> 2;
    const int quad = tid & 3;
    const float* ap0 = aB + (size_t)rowL * DMODEL + quad * 4;
    const float* ap1 = aB + (size_t)(rowL + 64) * DMODEL + quad * 4;
    const float* bp0 = bB + (size_t)rowL * DMODEL + quad * 4;
    const float* bp1 = bB + (size_t)(rowL + 64) * DMODEL + quad * 4;

    const uint32_t aLane = ((uint32_t)(wm * 64 + (lane & 7) + ((lane >> 3) & 1) * 8) * 12
                           + ((lane >> 4) & 1) * 4) * 4;
    const uint32_t bLane = ((uint32_t)(lane & 7) * 12 + ((lane >> 3) & 1) * 4) * 4;
    const uint32_t sA0 = (uint32_t)__cvta_generic_to_shared(&As[0][0][0]);
    const uint32_t sA1 = (uint32_t)__cvta_generic_to_shared(&As[1][0][0]);
    const uint32_t sW0 = (uint32_t)__cvta_generic_to_shared(&Ws[0][0][0]);
    const uint32_t sW1 = (uint32_t)__cvta_generic_to_shared(&Ws[1][0][0]);

    float4 va0 = *(const float4*)ap0;
    float4 va1 = *(const float4*)ap1;
    float4 vb0 = *(const float4*)bp0;
    float4 vb1 = *(const float4*)bp1;
    *(uint2*)&As[0][rowL][quad * 2]      = cvt4h(va0);
    *(uint2*)&As[0][rowL + 64][quad * 2] = cvt4h(va1);
    *(uint2*)&Ws[0][rowL][quad * 2]      = cvt4h(vb0);
    *(uint2*)&Ws[0][rowL + 64][quad * 2] = cvt4h(vb1);
    __syncthreads();

    for (int kt = 0; kt < KITERS; kt++) {
        const int cur = kt & 1;
        if (kt + 1 < KITERS) {
            const int kb = (kt + 1) * BKT;
            va0 = *(const float4*)(ap0 + kb);
            va1 = *(const float4*)(ap1 + kb);
            vb0 = *(const float4*)(bp0 + kb);
            vb1 = *(const float4*)(bp1 + kb);
        }
        const uint32_t sa = (cur ? sA1 : sA0) + aLane;
        const uint32_t sw = (cur ? sW1 : sW0) + bLane;
        uint32_t af[4][4], bf[4][2];
#pragma unroll
        for (int i = 0; i < 4; i++) ldsm_x4(af[i], sa + (uint32_t)(i * 16 * 48));
#pragma unroll
        for (int j = 0; j < 4; j++) ldsm_x2(bf[j], sw + (uint32_t)((wn * 32 + j * 8) * 48));
#pragma unroll
        for (int i = 0; i < 4; i++)
#pragma unroll
            for (int j = 0; j < 4; j++)
                mma_f16(acc[i][j], af[i], bf[j]);

        if (kt + 1 < KITERS) {
            const int nxt = (kt + 1) & 1;
            *(uint2*)&As[nxt][rowL][quad * 2]      = cvt4h(va0);
            *(uint2*)&As[nxt][rowL + 64][quad * 2] = cvt4h(va1);
            *(uint2*)&Ws[nxt][rowL][quad * 2]      = cvt4h(vb0);
            *(uint2*)&Ws[nxt][rowL + 64][quad * 2] = cvt4h(vb1);
        }
        __syncthreads();
    }
}

// ---------------------------------------------------------------------------
// Kernel 1: qkv GEMM. q,k -> [part][b][e][n]; v -> [bn][d] (token-major).
// ---------------------------------------------------------------------------
__global__ __launch_bounds__(256) void qkv_h16(const float* __restrict__ x,
                                               const float* __restrict__ w) {
    __shared__ __align__(16) uint32_t As[2][128][12];
    __shared__ __align__(16) uint32_t Ws[2][128][12];
    __shared__ __align__(16) float stage[32][132];

    const int tid  = threadIdx.x;
    const int lane = tid & 31;
    const int warp = tid >> 5;
    const int gid = lane >> 2, tig = lane & 3;
    const int wm = warp >> 2, wn = warp & 3;

    const size_t mBase = (size_t)blockIdx.y * 128;
    const int    eBase = blockIdx.x * 128;

    float acc[4][4][4];
    h16_loop(x + mBase * DMODEL, w + (size_t)eBase * DMODEL,
             (HTile*)As, (HTile*)Ws, acc, tid);

    if (eBase >= 768) {
        // v part: direct register stores, token-major [bn][d]
        const int dBase = eBase - 768;
#pragma unroll
        for (int i = 0; i < 4; i++) {
            size_t bn0 = mBase + wm * 64 + i * 16 + gid;
#pragma unroll
            for (int j = 0; j < 4; j++) {
                int d = dBase + wn * 32 + j * 8 + 2 * tig;
                float2 o0 = make_float2(acc[i][j][0], acc[i][j][1]);
                float2 o1 = make_float2(acc[i][j][2], acc[i][j][3]);
                *(float2*)(g_qkvV + bn0 * DMODEL + d)       = o0;
                *(float2*)(g_qkvV + (bn0 + 8) * DMODEL + d) = o1;
            }
        }
        return;
    }

    const size_t PART = (size_t)B_SZ * DMODEL * NTOK;
    for (int rnd = 0; rnd < 4; rnd++) {
        __syncthreads();
        if (wn == rnd) {
#pragma unroll
            for (int i = 0; i < 4; i++) {
                int m0 = wm * 64 + i * 16 + gid;
#pragma unroll
                for (int j = 0; j < 4; j++) {
                    int e0 = j * 8 + 2 * tig;
                    stage[e0][m0]         = acc[i][j][0];
                    stage[e0 + 1][m0]     = acc[i][j][1];
                    stage[e0][m0 + 8]     = acc[i][j][2];
                    stage[e0 + 1][m0 + 8] = acc[i][j][3];
                }
            }
        }
        __syncthreads();
        int tok4 = (tid & 31) * 4;
#pragma unroll
        for (int ii = 0; ii < 4; ii++) {
            int el = (tid >> 5) + 8 * ii;
            int eg = eBase + rnd * 32 + el;
            int part = eg / DMODEL, rr = eg % DMODEL;
            size_t bn = mBase + tok4;
            int b = (int)(bn / NTOK);
            int n = (int)(bn - (size_t)b * NTOK);
            *(float4*)(g_qkv + (size_t)part * PART + ((size_t)b * DMODEL + rr) * NTOK + n) =
                *(float4*)&stage[el][tok4];
        }
    }
}

// ---------------------------------------------------------------------------
// Kernel 3a: partial QK^T + fused sumsq partials. grid (7 chunks, 256 bh).
// ---------------------------------------------------------------------------
__global__ __launch_bounds__(256) void qk_partial() {
    const int chunk = blockIdx.x;
    const int bh    = blockIdx.y;
    const int b = bh >> 3, h = bh & 7;

    const size_t PART = (size_t)B_SZ * DMODEL * NTOK;
    const float* qp = g_qkv + ((size_t)b * DMODEL + h * CDIM) * NTOK;
    const float* kp = g_qkv + PART + ((size_t)b * DMODEL + h * CDIM) * NTOK;

    __shared__ float qs[48][65];
    __shared__ float ks[48][65];
    __shared__ float red[96][17];

    const int tid = threadIdx.x;
    const int tx = tid & 15;
    const int ty = tid >> 4;
    float acc[3][3];
    float sq[3] = {0.f, 0.f, 0.f}, sk[3] = {0.f, 0.f, 0.f};
#pragma unroll
    for (int i = 0; i < 3; i++)
#pragma unroll
        for (int j = 0; j < 3; j++) acc[i][j] = 0.f;

    const int nStart = chunk * 448;
    for (int n0 = nStart; n0 < nStart + 448; n0 += 64) {
        __syncthreads();
#pragma unroll
        for (int r = 0; r < 3; r++) {
            int v   = tid + r * 256;
            int row = v >> 4;
            int col = (v & 15) * 4;
            float4 tq = *(const float4*)(qp + (size_t)row * NTOK + n0 + col);
            qs[row][col + 0] = tq.x; qs[row][col + 1] = tq.y;
            qs[row][col + 2] = tq.z; qs[row][col + 3] = tq.w;
            sq[r] += tq.x * tq.x + tq.y * tq.y + tq.z * tq.z + tq.w * tq.w;
            float4 tk = *(const float4*)(kp + (size_t)row * NTOK + n0 + col);
            ks[row][col + 0] = tk.x; ks[row][col + 1] = tk.y;
            ks[row][col + 2] = tk.z; ks[row][col + 3] = tk.w;
            sk[r] += tk.x * tk.x + tk.y * tk.y + tk.z * tk.z + tk.w * tk.w;
        }
        __syncthreads();
#pragma unroll 8
        for (int kk = 0; kk < 64; kk++) {
            float a0 = qs[3 * ty + 0][kk];
            float a1 = qs[3 * ty + 1][kk];
            float a2 = qs[3 * ty + 2][kk];
            float b0 = ks[3 * tx + 0][kk];
            float b1 = ks[3 * tx + 1][kk];
            float b2 = ks[3 * tx + 2][kk];
            acc[0][0] = fmaf(a0, b0, acc[0][0]); acc[0][1] = fmaf(a0, b1, acc[0][1]); acc[0][2] = fmaf(a0, b2, acc[0][2]);
            acc[1][0] = fmaf(a1, b0, acc[1][0]); acc[1][1] = fmaf(a1, b1, acc[1][1]); acc[1][2] = fmaf(a1, b2, acc[1][2]);
            acc[2][0] = fmaf(a2, b0, acc[2][0]); acc[2][1] = fmaf(a2, b1, acc[2][1]); acc[2][2] = fmaf(a2, b2, acc[2][2]);
        }
    }

    float* dst = g_attnp + ((size_t)chunk * 256 + bh) * (CDIM * CDIM);
#pragma unroll
    for (int i = 0; i < 3; i++)
#pragma unroll
        for (int j = 0; j < 3; j++)
            dst[(3 * ty + i) * CDIM + 3 * tx + j] = acc[i][j];

    __syncthreads();
#pragma unroll
    for (int r = 0; r < 3; r++) {
        red[(tid >> 4) + 16 * r][tid & 15]      = sq[r];
        red[48 + (tid >> 4) + 16 * r][tid & 15] = sk[r];
    }
    __syncthreads();
    if (tid < 96) {
        float s = 0.f;
#pragma unroll
        for (int c = 0; c < 16; c++) s += red[tid][c];
        g_normp[((size_t)chunk * 256 + bh) * 96 + tid] = s;
    }
}

// ---------------------------------------------------------------------------
// Kernel 3b: reduce partials (attn + norms), scale, row softmax. 96 threads.
// ---------------------------------------------------------------------------
__global__ __launch_bounds__(96) void softmax_kernel(const float* __restrict__ temp) {
    const int bh = blockIdx.x;
    const int h = bh & 7;
    const int tid = threadIdx.x;

    __shared__ float kinv[48];

    float sn = 0.f;
#pragma unroll
    for (int p = 0; p < 7; p++)
        sn += g_normp[(size_t)p * 256 * 96 + (size_t)bh * 96 + tid];
    float inv_n = 1.0f / fmaxf(sqrtf(sn), 1e-12f);
    if (tid >= 48) kinv[tid - 48] = inv_n;
    __syncthreads();
    if (tid >= 48) return;

    const float qi = inv_n;
    const float tv = temp[h];
    const size_t base = (size_t)bh * (CDIM * CDIM) + (size_t)tid * CDIM;

    float r[48];
#pragma unroll
    for (int d = 0; d < 48; d++) {
        float s = 0.f;
#pragma unroll
        for (int p = 0; p < 7; p++)
            s += g_attnp[(size_t)p * 256 * CDIM * CDIM + base + d];
        r[d] = s * qi * kinv[d] * tv;
    }
    float m = -1e30f;
#pragma unroll
    for (int d = 0; d < 48; d++) m = fmaxf(m, r[d]);
    float s = 0.f;
#pragma unroll
    for (int d = 0; d < 48; d++) { r[d] = expf(r[d] - m); s += r[d]; }
    float inv = 1.0f / s;
#pragma unroll
    for (int d = 0; d < 48; d++) g_attn[base + d] = r[d] * inv;
}

// ---------------------------------------------------------------------------
// Kernel 3c: fold attn into proj weights.
// wEff[b][e][h*48+d] = sum_c wp[e][h*48+c] * attn[bh][c][d]
// ---------------------------------------------------------------------------
__global__ __launch_bounds__(256) void wfold(const float* __restrict__ wp) {
    const int bh = blockIdx.x;
    const int b = bh >> 3, h = bh & 7;
    const int tid = threadIdx.x;

    __shared__ float at[48][49];
    for (int v = tid; v < 48 * 48; v += 256)
        at[v / 48][v % 48] = g_attn[(size_t)bh * CDIM * CDIM + v];
    __syncthreads();

    for (int e = tid; e < DMODEL; e += 256) {
        float wrow[48];
#pragma unroll 12
        for (int c = 0; c < 48; c++) wrow[c] = wp[(size_t)e * DMODEL + h * CDIM + c];
        float out[48];
#pragma unroll
        for (int d = 0; d < 48; d++) out[d] = 0.f;
#pragma unroll 4
        for (int c = 0; c < 48; c++) {
            float wv = wrow[c];
#pragma unroll
            for (int d = 0; d < 48; d++) out[d] = fmaf(wv, at[c][d], out[d]);
        }
        float* dst = g_weff + ((size_t)b * DMODEL + e) * DMODEL + h * CDIM;
#pragma unroll
        for (int d4 = 0; d4 < 12; d4++)
            *(float4*)(dst + d4 * 4) = *(float4*)&out[d4 * 4];
    }
}

// ---------------------------------------------------------------------------
// Kernel 4: proj GEMM: y[bn,e] = v[bn,:] . wEff[b][e,:] + bias[e]
// grid (3 e-tiles, 32*25 bn-tiles). Tail tile (t=24) masked to 64 rows.
// ---------------------------------------------------------------------------
__global__ __launch_bounds__(256) void proj_h16(const float* __restrict__ bias,
                                                float* __restrict__ y) {
    __shared__ __align__(16) uint32_t As[2][128][12];
    __shared__ __align__(16) uint32_t Ws[2][128][12];

    const int tid  = threadIdx.x;
    const int lane = tid & 31;
    const int warp = tid >> 5;
    const int gid = lane >> 2, tig = lane & 3;
    const int wm = warp >> 2, wn = warp & 3;

    const int bt = blockIdx.y;
    const int b  = bt / 25;
    const int t  = bt - b * 25;
    const int valid = (t == 24) ? 64 : 128;
    const size_t mBase = (size_t)b * NTOK + t * 128;
    const int    eBase = blockIdx.x * 128;

    float acc[4][4][4];
    h16_loop(g_qkvV + mBase * DMODEL,
             g_weff + (size_t)b * DMODEL * DMODEL + (size_t)eBase * DMODEL,
             (HTile*)As, (HTile*)Ws, acc, tid);

#pragma unroll
    for (int i = 0; i < 4; i++) {
        int lr = wm * 64 + i * 16 + gid;
        size_t bn0 = mBase + lr;
#pragma unroll
        for (int j = 0; j < 4; j++) {
            int e = eBase + wn * 32 + j * 8 + 2 * tig;
            float2 b2 = *(const float2*)(bias + e);
            if (lr < valid) {
                float2 o0 = make_float2(acc[i][j][0] + b2.x, acc[i][j][1] + b2.y);
                *(float2*)(y + bn0 * DMODEL + e) = o0;
            }
            if (lr + 8 < valid) {
                float2 o1 = make_float2(acc[i][j][2] + b2.x, acc[i][j][3] + b2.y);
                *(float2*)(y + (bn0 + 8) * DMODEL + e) = o1;
            }
        }
    }
}

// ---------------------------------------------------------------------------
extern "C" void kernel_launch(void* const* d_in, const int* in_sizes, int n_in,
                              void* d_out, int out_size) {
    const float* x      = (const float*)d_in[0];
    const float* qkv_w  = (const float*)d_in[1];
    const float* temp   = (const float*)d_in[2];
    const float* proj_w = (const float*)d_in[3];
    const float* proj_b = (const float*)d_in[4];
    float* y = (float*)d_out;

    qkv_h16<<<dim3(9, 784), 256>>>(x, qkv_w);
    qk_partial<<<dim3(7, B_SZ * HEADS), 256>>>();
    softmax_kernel<<<B_SZ * HEADS, 96>>>(temp);
    wfold<<<B_SZ * HEADS, 256>>>(proj_w);
    proj_h16<<<dim3(3, 32 * 25), 256>>>(proj_b, y);
}